// round 8
// baseline (speedup 1.0000x reference)
#include <cuda_runtime.h>
#include <math.h>

#define NN       1024
#define NEVALC   131072
#define NPOLES   8
#define NGROUPS  256          // 4 nodes per group
#define LOGC     700.0f      // fixed log-shift (cancels in num/den); keeps expf in range

typedef unsigned long long ull;

// ---------------- compile-time Chebyshev nodes --------------------------------------
// Nodes are input-independent. constexpr cospi (Taylor, |err| ~1e-17) reproduces the
// fp64-cos -> f32 node bits used by every passing round. No runtime kernel needed.
constexpr double CPI = 3.141592653589793238462643383279502884;
constexpr double ccos_t(double z) {            // |z| <= pi/4
    double t = 1.0, s = 1.0, z2 = z * z;
    for (int k = 1; k <= 12; k++) { t *= -z2 / ((2.0 * k - 1.0) * (2.0 * k)); s += t; }
    return s;
}
constexpr double csin_t(double z) {            // |z| <= pi/4
    double t = z, s = z, z2 = z * z;
    for (int k = 1; k <= 12; k++) { t *= -z2 / ((2.0 * k) * (2.0 * k + 1.0)); s += t; }
    return s;
}
constexpr double cospi_c(double x) {           // x in [0,1]
    double r = x; bool neg = false;
    if (r > 0.5) { r = 1.0 - r; neg = true; }
    double v = (r <= 0.25) ? ccos_t(CPI * r) : csin_t(CPI * (0.5 - r));
    return neg ? -v : v;
}
struct alignas(16) NodeTab { float v[NN]; };
constexpr NodeTab mk_nodes() {
    NodeTab n{};
    for (int i = 0; i < NN; i++) n.v[i] = (float)cospi_c((double)i / 1023.0);
    return n;
}
__device__ constexpr NodeTab c_nodes = mk_nodes();

// ---------------- scratch (no allocations allowed) ----------------
__device__ ulonglong2 g_coef[NGROUPS * 7];   // 14 packed-duplicated f32x2 coeffs per group

// ---------------- helpers ----------------
__device__ __forceinline__ ull pk2(float lo, float hi) {
    ull r; asm("mov.b64 %0,{%1,%2};" : "=l"(r) : "f"(lo), "f"(hi)); return r;
}
__device__ __forceinline__ void upk2(ull v, float& lo, float& hi) {
    asm("mov.b64 {%0,%1},%2;" : "=f"(lo), "=f"(hi) : "l"(v));
}
__device__ __forceinline__ ull f2add(ull a, ull b) {
    ull d; asm("add.rn.f32x2 %0,%1,%2;" : "=l"(d) : "l"(a), "l"(b)); return d;
}
__device__ __forceinline__ float frcp(float a) {
    float r; asm("rcp.approx.f32 %0,%1;" : "=f"(r) : "f"(a)); return r;
}

// ---------------- P0: weights + group coefficients ----------------------------------
// grid 128 x block 256. Block b owns nodes 8b..8b+7 and groups 2b, 2b+1.
__global__ __launch_bounds__(256) void k_prep(const float* __restrict__ vals,
                                              const float* __restrict__ pr,
                                              const float* __restrict__ pim) {
    __shared__ float snodes[NN];
    __shared__ float sw[8];
    int tid = threadIdx.x;

    // node table from the compile-time constant
    {
        const float4* src = (const float4*)c_nodes.v;
        float4* dst = (float4*)snodes;
        dst[tid] = src[tid];                 // 256 threads x 4 floats = 1024
    }
    __syncthreads();

    // weights: one warp per node; f32 log-sum (reference math). The max-
    // normalization is a COMMON factor and cancels in num/den -> fixed LOGC.
    int w  = tid >> 5;
    int ln = tid & 31;
    int j  = blockIdx.x * 8 + w;
    float nj = snodes[j];
    float s = 0.f;
    #pragma unroll 8
    for (int i = ln; i < NN; i += 32)
        if (i != j) s += logf(fabsf(nj - snodes[i]));
    #pragma unroll
    for (int off = 16; off; off >>= 1) s += __shfl_xor_sync(0xffffffffu, s, off);
    if (ln == 0) {
        float ps = 0.f;
        #pragma unroll
        for (int p = 0; p < NPOLES; p++) {
            float dr = nj - pr[p];
            ps += logf(dr * dr + pim[p] * pim[p]);
        }
        float wv = expf(ps - s - LOGC);
        sw[w] = (j & 1) ? -wv : wv;     // sign = (-1)^j (nodes strictly descending)
    }
    __syncthreads();

    // group-rational coefficients (fp64 build -> f32 packed), 2 groups/block.
    //   Q(t)  = prod (t - d_i)                     (monic quartic)
    //   Pv(t) = sum v_i*w_i * prod_{j!=i}(t - d_j) (cubic)
    //   Pw(t) = sum     w_i * prod_{j!=i}(t - d_j) (cubic)
    if (tid < 2) {
        int g = blockIdx.x * 2 + tid;
        double n[4], d[4], u[4], uv[4];
        #pragma unroll
        for (int i = 0; i < 4; i++) n[i] = (double)snodes[4 * g + i];
        float cf = (float)(0.25 * (n[0] + n[1] + n[2] + n[3]));
        #pragma unroll
        for (int i = 0; i < 4; i++) {
            d[i]  = n[i] - (double)cf;
            u[i]  = (double)sw[4 * tid + i];
            uv[i] = u[i] * (double)vals[4 * g + i];
        }
        double e1 = d[0] + d[1] + d[2] + d[3];
        double e2 = d[0]*d[1] + d[0]*d[2] + d[0]*d[3] + d[1]*d[2] + d[1]*d[3] + d[2]*d[3];
        double e3 = d[0]*d[1]*d[2] + d[0]*d[1]*d[3] + d[0]*d[2]*d[3] + d[1]*d[2]*d[3];
        double e4 = d[0]*d[1]*d[2]*d[3];
        double pv3 = 0, pv2 = 0, pv1 = 0, pv0 = 0;
        double pw3 = 0, pw2 = 0, pw1 = 0, pw0 = 0;
        #pragma unroll
        for (int i = 0; i < 4; i++) {
            double s1 = e1 - d[i];          // elementary syms of the 3 other roots
            double s2 = e2 - d[i] * s1;
            double s3 = e3 - d[i] * s2;
            pv3 += uv[i];  pv2 -= uv[i] * s1;  pv1 += uv[i] * s2;  pv0 -= uv[i] * s3;
            pw3 += u[i];   pw2 -= u[i]  * s1;  pw1 += u[i]  * s2;  pw0 -= u[i]  * s3;
        }
        ull* cc = (ull*)g_coef + (size_t)g * 14;
        float f;
        f = -cf;          cc[0]  = pk2(f, f);
        f = (float)(-e1); cc[1]  = pk2(f, f);   // q3
        f = (float)( e2); cc[2]  = pk2(f, f);   // q2
        f = (float)(-e3); cc[3]  = pk2(f, f);   // q1
        f = (float)( e4); cc[4]  = pk2(f, f);   // q0
        f = (float)pv3;   cc[5]  = pk2(f, f);
        f = (float)pv2;   cc[6]  = pk2(f, f);
        f = (float)pv1;   cc[7]  = pk2(f, f);
        f = (float)pv0;   cc[8]  = pk2(f, f);
        f = (float)pw3;   cc[9]  = pk2(f, f);
        f = (float)pw2;   cc[10] = pk2(f, f);
        f = (float)pw1;   cc[11] = pk2(f, f);
        f = (float)pw0;   cc[12] = pk2(f, f);
        cc[13] = 0ull;                          // pad to 7 x 16B
    }
}

// ---------------- main eval: 8 pts/thread (4 pairs), split-4 over groups ------------
// block 512 = 4 partitions x 128 point-lanes, grid 128 (1 CTA/SM, 16 warps).
// The WHOLE per-group body (4 pairs x (11 FFMA2/ADD2 + 2 RCP) + accumulate) is a
// single asm block: no inter-asm register-pair marshaling, so the only non-math
// instructions per iteration are the 7 LDS.128 and loop control.
__global__ __launch_bounds__(512) void k_eval(const float* __restrict__ x,
                                              float* __restrict__ out) {
    __shared__ ulonglong2 sc[NGROUPS * 7];     // 28 KB coeffs (reused as reduction buf)
    {
        const uint4* src = (const uint4*)g_coef;
        uint4* dst = (uint4*)sc;
        #pragma unroll
        for (int i = threadIdx.x; i < NGROUPS * 7; i += 512) dst[i] = src[i];
    }
    __syncthreads();

    int t    = threadIdx.x;
    int part = t >> 7;                      // group partition 0..3
    int lane = t & 127;                     // point-lane
    int quad0 = blockIdx.x * 256 + lane;    // coalesced float4 accesses
    int quad1 = quad0 + 128;
    float4 a = ((const float4*)x)[quad0];
    float4 b = ((const float4*)x)[quad1];
    ull xp0 = pk2(a.x, a.y), xp1 = pk2(a.z, a.w);
    ull xp2 = pk2(b.x, b.y), xp3 = pk2(b.z, b.w);
    ull nm0 = 0, dn0 = 0, nm1 = 0, dn1 = 0, nm2 = 0, dn2 = 0, nm3 = 0, dn3 = 0;

    const ulonglong2* cp = sc + part * 64 * 7;

    #pragma unroll 4
    for (int g = 0; g < 64; g++) {
        ulonglong2 c0 = cp[0], c1 = cp[1], c2 = cp[2], c3 = cp[3],
                   c4 = cp[4], c5 = cp[5], c6 = cp[6];
        cp += 7;
        // %0-%7  : nm0 dn0 nm1 dn1 nm2 dn2 nm3 dn3   (in-out)
        // %8-%11 : x0 x1 x2 x3
        // %12-%24: cM q3 q2 q1 q0 pv3 pv2 pv1 pv0 pw3 pw2 pw1 pw0
        asm("{\n\t"
            ".reg .b64 T0,T1,T2,T3,Q0,Q1,Q2,Q3,V0,V1,V2,V3,W0,W1,W2,W3,R0,R1,R2,R3;\n\t"
            ".reg .f32 a0,b0,a1,b1,a2,b2,a3,b3;\n\t"
            "add.rn.f32x2 T0, %8,  %12;\n\t"
            "add.rn.f32x2 T1, %9,  %12;\n\t"
            "add.rn.f32x2 T2, %10, %12;\n\t"
            "add.rn.f32x2 T3, %11, %12;\n\t"
            "add.rn.f32x2 Q0, T0, %13;\n\t"
            "add.rn.f32x2 Q1, T1, %13;\n\t"
            "add.rn.f32x2 Q2, T2, %13;\n\t"
            "add.rn.f32x2 Q3, T3, %13;\n\t"
            "fma.rn.f32x2 Q0, Q0, T0, %14;\n\t"
            "fma.rn.f32x2 Q1, Q1, T1, %14;\n\t"
            "fma.rn.f32x2 Q2, Q2, T2, %14;\n\t"
            "fma.rn.f32x2 Q3, Q3, T3, %14;\n\t"
            "fma.rn.f32x2 Q0, Q0, T0, %15;\n\t"
            "fma.rn.f32x2 Q1, Q1, T1, %15;\n\t"
            "fma.rn.f32x2 Q2, Q2, T2, %15;\n\t"
            "fma.rn.f32x2 Q3, Q3, T3, %15;\n\t"
            "fma.rn.f32x2 Q0, Q0, T0, %16;\n\t"
            "fma.rn.f32x2 Q1, Q1, T1, %16;\n\t"
            "fma.rn.f32x2 Q2, Q2, T2, %16;\n\t"
            "fma.rn.f32x2 Q3, Q3, T3, %16;\n\t"
            "mov.b64 {a0,b0}, Q0;\n\t"
            "mov.b64 {a1,b1}, Q1;\n\t"
            "mov.b64 {a2,b2}, Q2;\n\t"
            "mov.b64 {a3,b3}, Q3;\n\t"
            "rcp.approx.f32 a0, a0;\n\t"
            "rcp.approx.f32 b0, b0;\n\t"
            "rcp.approx.f32 a1, a1;\n\t"
            "rcp.approx.f32 b1, b1;\n\t"
            "rcp.approx.f32 a2, a2;\n\t"
            "rcp.approx.f32 b2, b2;\n\t"
            "rcp.approx.f32 a3, a3;\n\t"
            "rcp.approx.f32 b3, b3;\n\t"
            "mov.b64 R0, {a0,b0};\n\t"
            "mov.b64 R1, {a1,b1};\n\t"
            "mov.b64 R2, {a2,b2};\n\t"
            "mov.b64 R3, {a3,b3};\n\t"
            "fma.rn.f32x2 V0, %17, T0, %18;\n\t"
            "fma.rn.f32x2 V1, %17, T1, %18;\n\t"
            "fma.rn.f32x2 V2, %17, T2, %18;\n\t"
            "fma.rn.f32x2 V3, %17, T3, %18;\n\t"
            "fma.rn.f32x2 V0, V0, T0, %19;\n\t"
            "fma.rn.f32x2 V1, V1, T1, %19;\n\t"
            "fma.rn.f32x2 V2, V2, T2, %19;\n\t"
            "fma.rn.f32x2 V3, V3, T3, %19;\n\t"
            "fma.rn.f32x2 V0, V0, T0, %20;\n\t"
            "fma.rn.f32x2 V1, V1, T1, %20;\n\t"
            "fma.rn.f32x2 V2, V2, T2, %20;\n\t"
            "fma.rn.f32x2 V3, V3, T3, %20;\n\t"
            "fma.rn.f32x2 W0, %21, T0, %22;\n\t"
            "fma.rn.f32x2 W1, %21, T1, %22;\n\t"
            "fma.rn.f32x2 W2, %21, T2, %22;\n\t"
            "fma.rn.f32x2 W3, %21, T3, %22;\n\t"
            "fma.rn.f32x2 W0, W0, T0, %23;\n\t"
            "fma.rn.f32x2 W1, W1, T1, %23;\n\t"
            "fma.rn.f32x2 W2, W2, T2, %23;\n\t"
            "fma.rn.f32x2 W3, W3, T3, %23;\n\t"
            "fma.rn.f32x2 W0, W0, T0, %24;\n\t"
            "fma.rn.f32x2 W1, W1, T1, %24;\n\t"
            "fma.rn.f32x2 W2, W2, T2, %24;\n\t"
            "fma.rn.f32x2 W3, W3, T3, %24;\n\t"
            "fma.rn.f32x2 %0, V0, R0, %0;\n\t"
            "fma.rn.f32x2 %1, W0, R0, %1;\n\t"
            "fma.rn.f32x2 %2, V1, R1, %2;\n\t"
            "fma.rn.f32x2 %3, W1, R1, %3;\n\t"
            "fma.rn.f32x2 %4, V2, R2, %4;\n\t"
            "fma.rn.f32x2 %5, W2, R2, %5;\n\t"
            "fma.rn.f32x2 %6, V3, R3, %6;\n\t"
            "fma.rn.f32x2 %7, W3, R3, %7;\n\t"
            "}"
            : "+l"(nm0), "+l"(dn0), "+l"(nm1), "+l"(dn1),
              "+l"(nm2), "+l"(dn2), "+l"(nm3), "+l"(dn3)
            : "l"(xp0), "l"(xp1), "l"(xp2), "l"(xp3),
              "l"(c0.x), "l"(c0.y), "l"(c1.x), "l"(c1.y), "l"(c2.x),
              "l"(c2.y), "l"(c3.x), "l"(c3.y), "l"(c4.x),
              "l"(c4.y), "l"(c5.x), "l"(c5.y), "l"(c6.x));
    }

    // cross-partition reduction: reuse sc as the partial buffer (all coeff
    // reads are complete after this barrier).
    __syncthreads();
    ull (*sred)[128][8] = (ull(*)[128][8])sc;   // 3 x 128 x 8 x 8B = 24 KB <= 28 KB
    if (part) {
        ull* dst = sred[part - 1][lane];
        dst[0] = nm0; dst[1] = dn0; dst[2] = nm1; dst[3] = dn1;
        dst[4] = nm2; dst[5] = dn2; dst[6] = nm3; dst[7] = dn3;
    }
    __syncthreads();
    if (part == 0) {
        #pragma unroll
        for (int p = 0; p < 3; p++) {
            const ull* s = sred[p][lane];
            nm0 = f2add(nm0, s[0]); dn0 = f2add(dn0, s[1]);
            nm1 = f2add(nm1, s[2]); dn1 = f2add(dn1, s[3]);
            nm2 = f2add(nm2, s[4]); dn2 = f2add(dn2, s[5]);
            nm3 = f2add(nm3, s[6]); dn3 = f2add(dn3, s[7]);
        }
        float n0, n1, d0, d1;
        float4 o;
        upk2(nm0, n0, n1); upk2(dn0, d0, d1);
        o.x = n0 * frcp(d0); o.y = n1 * frcp(d1);
        upk2(nm1, n0, n1); upk2(dn1, d0, d1);
        o.z = n0 * frcp(d0); o.w = n1 * frcp(d1);
        ((float4*)out)[quad0] = o;
        upk2(nm2, n0, n1); upk2(dn2, d0, d1);
        o.x = n0 * frcp(d0); o.y = n1 * frcp(d1);
        upk2(nm3, n0, n1); upk2(dn3, d0, d1);
        o.z = n0 * frcp(d0); o.w = n1 * frcp(d1);
        ((float4*)out)[quad1] = o;
    }
}

// ---------------- launch ----------------
extern "C" void kernel_launch(void* const* d_in, const int* in_sizes, int n_in,
                              void* d_out, int out_size) {
    const float* x    = (const float*)d_in[0];
    const float* vals = (const float*)d_in[1];
    const float* pr   = (const float*)d_in[2];
    const float* pim  = (const float*)d_in[3];
    float* out = (float*)d_out;

    k_prep<<<128, 256>>>(vals, pr, pim);
    k_eval<<<128, 512>>>(x, out);
}

// round 9
// speedup vs baseline: 1.0557x; 1.0557x over previous
#include <cuda_runtime.h>
#include <math.h>

#define NN       1024
#define NEVALC   131072
#define NPOLES   8
#define NGROUPS  256          // 4 nodes per group
#define GRID     128
#define BLOCK    512
#define LOGC     700.0f      // fixed log-shift (cancels in num/den); keeps expf in range

typedef unsigned long long ull;

// ---------------- compile-time Chebyshev nodes --------------------------------------
// Nodes are input-independent. constexpr cospi (Taylor, |err| ~1e-17) reproduces the
// fp64-cos -> f32 node bits used by every passing round.
constexpr double CPI = 3.141592653589793238462643383279502884;
constexpr double ccos_t(double z) {            // |z| <= pi/4
    double t = 1.0, s = 1.0, z2 = z * z;
    for (int k = 1; k <= 12; k++) { t *= -z2 / ((2.0 * k - 1.0) * (2.0 * k)); s += t; }
    return s;
}
constexpr double csin_t(double z) {            // |z| <= pi/4
    double t = z, s = z, z2 = z * z;
    for (int k = 1; k <= 12; k++) { t *= -z2 / ((2.0 * k) * (2.0 * k + 1.0)); s += t; }
    return s;
}
constexpr double cospi_c(double x) {           // x in [0,1]
    double r = x; bool neg = false;
    if (r > 0.5) { r = 1.0 - r; neg = true; }
    double v = (r <= 0.25) ? ccos_t(CPI * r) : csin_t(CPI * (0.5 - r));
    return neg ? -v : v;
}
struct alignas(16) NodeTab { float v[NN]; };
constexpr NodeTab mk_nodes() {
    NodeTab n{};
    for (int i = 0; i < NN; i++) n.v[i] = (float)cospi_c((double)i / 1023.0);
    return n;
}
__device__ constexpr NodeTab c_nodes = mk_nodes();

// ---------------- scratch (no allocations allowed) ----------------
__device__ ulonglong2 g_coef[NGROUPS * 7];   // 14 packed-duplicated f32x2 coeffs per group
__device__ unsigned   g_bar;                  // monotonic grid-barrier ticket counter

// ---------------- helpers ----------------
__device__ __forceinline__ ull pk2(float lo, float hi) {
    ull r; asm("mov.b64 %0,{%1,%2};" : "=l"(r) : "f"(lo), "f"(hi)); return r;
}
__device__ __forceinline__ void upk2(ull v, float& lo, float& hi) {
    asm("mov.b64 {%0,%1},%2;" : "=f"(lo), "=f"(hi) : "l"(v));
}
__device__ __forceinline__ ull f2add(ull a, ull b) {
    ull d; asm("add.rn.f32x2 %0,%1,%2;" : "=l"(d) : "l"(a), "l"(b)); return d;
}
__device__ __forceinline__ float frcp(float a) {
    float r; asm("rcp.approx.f32 %0,%1;" : "=f"(r) : "f"(a)); return r;
}
__device__ __forceinline__ unsigned ldacq(unsigned* p) {
    unsigned v; asm volatile("ld.acquire.gpu.u32 %0,[%1];" : "=r"(v) : "l"(p)); return v;
}

// ---------------- fused kernel: prep + grid barrier + eval --------------------------
// grid 128 x block 512 -> exactly 1 resident block per SM (register-bound), so the
// software grid barrier cannot deadlock. Ticket counter is monotonic across graph
// replays (target derived from own ticket), so no reset is needed.
__global__ __launch_bounds__(512) void k_all(const float* __restrict__ x,
                                             const float* __restrict__ vals,
                                             const float* __restrict__ pr,
                                             const float* __restrict__ pim,
                                             float* __restrict__ out) {
    __shared__ float snodes[NN];
    __shared__ float sw[8];
    __shared__ float spart[8];
    __shared__ ulonglong2 sc[NGROUPS * 7];     // 28 KB coeffs (later reused for reduction)

    int tid = threadIdx.x;
    int w   = tid >> 5;
    int ln  = tid & 31;

    // ---- node table from the compile-time constant ----
    ((float2*)snodes)[tid] = ((const float2*)c_nodes.v)[tid];
    __syncthreads();

    // ---- weights: 2 warps per node (block owns nodes 8b..8b+7) ----
    // f32 log-sum per reference; the max-normalization is a COMMON factor across
    // nodes and cancels in num/den -> fixed LOGC shift, no global reduction.
    {
        int j = blockIdx.x * 8 + (w & 7);
        int h = w >> 3;                        // which half of the i-range
        float nj = snodes[j];
        float s = 0.f;
        #pragma unroll 4
        for (int i = ln + 32 * h; i < NN; i += 64)
            if (i != j) s += logf(fabsf(nj - snodes[i]));
        #pragma unroll
        for (int off = 16; off; off >>= 1) s += __shfl_xor_sync(0xffffffffu, s, off);
        if (ln == 0 && h == 1) spart[w & 7] = s;
        __syncthreads();
        if (ln == 0 && h == 0) {
            s += spart[w];
            float ps = 0.f;
            #pragma unroll
            for (int p = 0; p < NPOLES; p++) {
                float dr = nj - pr[p];
                ps += logf(dr * dr + pim[p] * pim[p]);
            }
            float wv = expf(ps - s - LOGC);
            sw[w] = (j & 1) ? -wv : wv;        // sign = (-1)^j (nodes strictly descending)
        }
    }
    __syncthreads();

    // ---- group-rational coefficients (fp64, 4 lanes per group, 2 groups/block) ----
    //   Q(t)  = prod (t - d_i)                     (monic quartic)
    //   Pv(t) = sum v_i*w_i * prod_{j!=i}(t - d_j) (cubic)
    //   Pw(t) = sum     w_i * prod_{j!=i}(t - d_j) (cubic)
    if (tid < 8) {
        int g  = blockIdx.x * 2 + (tid >> 2);
        int i  = tid & 3;
        double n[4];
        #pragma unroll
        for (int k = 0; k < 4; k++) n[k] = (double)snodes[4 * g + k];
        float cf = (float)(0.25 * (n[0] + n[1] + n[2] + n[3]));
        double d[4];
        #pragma unroll
        for (int k = 0; k < 4; k++) d[k] = n[k] - (double)cf;
        double e1 = d[0] + d[1] + d[2] + d[3];
        double e2 = d[0]*d[1] + d[0]*d[2] + d[0]*d[3] + d[1]*d[2] + d[1]*d[3] + d[2]*d[3];
        double e3 = d[0]*d[1]*d[2] + d[0]*d[1]*d[3] + d[0]*d[2]*d[3] + d[1]*d[2]*d[3];
        double e4 = d[0]*d[1]*d[2]*d[3];
        // own-root contribution
        double u  = (double)sw[(tid >> 2) * 4 + i];
        double uv = u * (double)vals[4 * g + i];
        double s1 = e1 - d[i];                 // elementary syms of the 3 other roots
        double s2 = e2 - d[i] * s1;
        double s3 = e3 - d[i] * s2;
        double red[8] = { uv, -uv * s1,  uv * s2, -uv * s3,
                          u,  -u  * s1,  u  * s2, -u  * s3 };
        #pragma unroll
        for (int k = 0; k < 8; k++) {
            red[k] += __shfl_down_sync(0xffu, red[k], 2, 4);
            red[k] += __shfl_down_sync(0xffu, red[k], 1, 4);
        }
        if (i == 0) {
            ull* cc = (ull*)g_coef + (size_t)g * 14;
            float f;
            f = -cf;              cc[0]  = pk2(f, f);
            f = (float)(-e1);     cc[1]  = pk2(f, f);   // q3
            f = (float)( e2);     cc[2]  = pk2(f, f);   // q2
            f = (float)(-e3);     cc[3]  = pk2(f, f);   // q1
            f = (float)( e4);     cc[4]  = pk2(f, f);   // q0
            f = (float)red[0];    cc[5]  = pk2(f, f);   // pv3
            f = (float)red[1];    cc[6]  = pk2(f, f);
            f = (float)red[2];    cc[7]  = pk2(f, f);
            f = (float)red[3];    cc[8]  = pk2(f, f);
            f = (float)red[4];    cc[9]  = pk2(f, f);   // pw3
            f = (float)red[5];    cc[10] = pk2(f, f);
            f = (float)red[6];    cc[11] = pk2(f, f);
            f = (float)red[7];    cc[12] = pk2(f, f);
            cc[13] = 0ull;
            __threadfence();                   // release own coeffs before barrier
        }
    }

    // ---- x loads (independent of coefficients; hide behind the barrier) ----
    int part  = tid >> 7;                      // group partition 0..3
    int lane  = tid & 127;                     // point-lane
    int quad0 = blockIdx.x * 256 + lane;       // coalesced float4 accesses
    int quad1 = quad0 + 128;
    float4 a = ((const float4*)x)[quad0];
    float4 b = ((const float4*)x)[quad1];
    ull xp0 = pk2(a.x, a.y), xp1 = pk2(a.z, a.w);
    ull xp2 = pk2(b.x, b.y), xp3 = pk2(b.z, b.w);

    // ---- grid barrier (monotonic tickets; 1 block/SM -> all resident) ----
    __syncthreads();
    if (tid == 0) {
        unsigned ticket = atomicAdd(&g_bar, 1u);
        unsigned target = (ticket / GRID + 1u) * GRID;
        while (ldacq(&g_bar) < target) { }
    }
    __syncthreads();

    // ---- load all 256 groups' coefficients into smem ----
    {
        const uint4* src = (const uint4*)g_coef;
        uint4* dst = (uint4*)sc;
        #pragma unroll
        for (int i = tid; i < NGROUPS * 7; i += BLOCK) dst[i] = src[i];
    }
    __syncthreads();

    // ---- eval: 8 pts/thread (4 packed pairs), split-4 over groups ----
    ull nm0 = 0, dn0 = 0, nm1 = 0, dn1 = 0, nm2 = 0, dn2 = 0, nm3 = 0, dn3 = 0;
    const ulonglong2* cp = sc + part * 64 * 7;

    #pragma unroll 4
    for (int g = 0; g < 64; g++) {
        ulonglong2 c0 = cp[0], c1 = cp[1], c2 = cp[2], c3 = cp[3],
                   c4 = cp[4], c5 = cp[5], c6 = cp[6];
        cp += 7;
        // %0-%7: accumulators, %8-%11: packed x, %12-%24: coefficients
        asm("{\n\t"
            ".reg .b64 T0,T1,T2,T3,Q0,Q1,Q2,Q3,V0,V1,V2,V3,W0,W1,W2,W3,R0,R1,R2,R3;\n\t"
            ".reg .f32 a0,b0,a1,b1,a2,b2,a3,b3;\n\t"
            "add.rn.f32x2 T0, %8,  %12;\n\t"
            "add.rn.f32x2 T1, %9,  %12;\n\t"
            "add.rn.f32x2 T2, %10, %12;\n\t"
            "add.rn.f32x2 T3, %11, %12;\n\t"
            "add.rn.f32x2 Q0, T0, %13;\n\t"
            "add.rn.f32x2 Q1, T1, %13;\n\t"
            "add.rn.f32x2 Q2, T2, %13;\n\t"
            "add.rn.f32x2 Q3, T3, %13;\n\t"
            "fma.rn.f32x2 Q0, Q0, T0, %14;\n\t"
            "fma.rn.f32x2 Q1, Q1, T1, %14;\n\t"
            "fma.rn.f32x2 Q2, Q2, T2, %14;\n\t"
            "fma.rn.f32x2 Q3, Q3, T3, %14;\n\t"
            "fma.rn.f32x2 Q0, Q0, T0, %15;\n\t"
            "fma.rn.f32x2 Q1, Q1, T1, %15;\n\t"
            "fma.rn.f32x2 Q2, Q2, T2, %15;\n\t"
            "fma.rn.f32x2 Q3, Q3, T3, %15;\n\t"
            "fma.rn.f32x2 Q0, Q0, T0, %16;\n\t"
            "fma.rn.f32x2 Q1, Q1, T1, %16;\n\t"
            "fma.rn.f32x2 Q2, Q2, T2, %16;\n\t"
            "fma.rn.f32x2 Q3, Q3, T3, %16;\n\t"
            "mov.b64 {a0,b0}, Q0;\n\t"
            "mov.b64 {a1,b1}, Q1;\n\t"
            "mov.b64 {a2,b2}, Q2;\n\t"
            "mov.b64 {a3,b3}, Q3;\n\t"
            "rcp.approx.f32 a0, a0;\n\t"
            "rcp.approx.f32 b0, b0;\n\t"
            "rcp.approx.f32 a1, a1;\n\t"
            "rcp.approx.f32 b1, b1;\n\t"
            "rcp.approx.f32 a2, a2;\n\t"
            "rcp.approx.f32 b2, b2;\n\t"
            "rcp.approx.f32 a3, a3;\n\t"
            "rcp.approx.f32 b3, b3;\n\t"
            "mov.b64 R0, {a0,b0};\n\t"
            "mov.b64 R1, {a1,b1};\n\t"
            "mov.b64 R2, {a2,b2};\n\t"
            "mov.b64 R3, {a3,b3};\n\t"
            "fma.rn.f32x2 V0, %17, T0, %18;\n\t"
            "fma.rn.f32x2 V1, %17, T1, %18;\n\t"
            "fma.rn.f32x2 V2, %17, T2, %18;\n\t"
            "fma.rn.f32x2 V3, %17, T3, %18;\n\t"
            "fma.rn.f32x2 V0, V0, T0, %19;\n\t"
            "fma.rn.f32x2 V1, V1, T1, %19;\n\t"
            "fma.rn.f32x2 V2, V2, T2, %19;\n\t"
            "fma.rn.f32x2 V3, V3, T3, %19;\n\t"
            "fma.rn.f32x2 V0, V0, T0, %20;\n\t"
            "fma.rn.f32x2 V1, V1, T1, %20;\n\t"
            "fma.rn.f32x2 V2, V2, T2, %20;\n\t"
            "fma.rn.f32x2 V3, V3, T3, %20;\n\t"
            "fma.rn.f32x2 W0, %21, T0, %22;\n\t"
            "fma.rn.f32x2 W1, %21, T1, %22;\n\t"
            "fma.rn.f32x2 W2, %21, T2, %22;\n\t"
            "fma.rn.f32x2 W3, %21, T3, %22;\n\t"
            "fma.rn.f32x2 W0, W0, T0, %23;\n\t"
            "fma.rn.f32x2 W1, W1, T1, %23;\n\t"
            "fma.rn.f32x2 W2, W2, T2, %23;\n\t"
            "fma.rn.f32x2 W3, W3, T3, %23;\n\t"
            "fma.rn.f32x2 W0, W0, T0, %24;\n\t"
            "fma.rn.f32x2 W1, W1, T1, %24;\n\t"
            "fma.rn.f32x2 W2, W2, T2, %24;\n\t"
            "fma.rn.f32x2 W3, W3, T3, %24;\n\t"
            "fma.rn.f32x2 %0, V0, R0, %0;\n\t"
            "fma.rn.f32x2 %1, W0, R0, %1;\n\t"
            "fma.rn.f32x2 %2, V1, R1, %2;\n\t"
            "fma.rn.f32x2 %3, W1, R1, %3;\n\t"
            "fma.rn.f32x2 %4, V2, R2, %4;\n\t"
            "fma.rn.f32x2 %5, W2, R2, %5;\n\t"
            "fma.rn.f32x2 %6, V3, R3, %6;\n\t"
            "fma.rn.f32x2 %7, W3, R3, %7;\n\t"
            "}"
            : "+l"(nm0), "+l"(dn0), "+l"(nm1), "+l"(dn1),
              "+l"(nm2), "+l"(dn2), "+l"(nm3), "+l"(dn3)
            : "l"(xp0), "l"(xp1), "l"(xp2), "l"(xp3),
              "l"(c0.x), "l"(c0.y), "l"(c1.x), "l"(c1.y), "l"(c2.x),
              "l"(c2.y), "l"(c3.x), "l"(c3.y), "l"(c4.x),
              "l"(c4.y), "l"(c5.x), "l"(c5.y), "l"(c6.x));
    }

    // ---- cross-partition reduction (reuse sc) + divide + store ----
    __syncthreads();
    ull (*sred)[128][8] = (ull(*)[128][8])sc;   // 3 x 128 x 8 x 8B = 24 KB <= 28 KB
    if (part) {
        ull* dst = sred[part - 1][lane];
        dst[0] = nm0; dst[1] = dn0; dst[2] = nm1; dst[3] = dn1;
        dst[4] = nm2; dst[5] = dn2; dst[6] = nm3; dst[7] = dn3;
    }
    __syncthreads();
    if (part == 0) {
        #pragma unroll
        for (int p = 0; p < 3; p++) {
            const ull* s = sred[p][lane];
            nm0 = f2add(nm0, s[0]); dn0 = f2add(dn0, s[1]);
            nm1 = f2add(nm1, s[2]); dn1 = f2add(dn1, s[3]);
            nm2 = f2add(nm2, s[4]); dn2 = f2add(dn2, s[5]);
            nm3 = f2add(nm3, s[6]); dn3 = f2add(dn3, s[7]);
        }
        float n0, n1, d0, d1;
        float4 o;
        upk2(nm0, n0, n1); upk2(dn0, d0, d1);
        o.x = n0 * frcp(d0); o.y = n1 * frcp(d1);
        upk2(nm1, n0, n1); upk2(dn1, d0, d1);
        o.z = n0 * frcp(d0); o.w = n1 * frcp(d1);
        ((float4*)out)[quad0] = o;
        upk2(nm2, n0, n1); upk2(dn2, d0, d1);
        o.x = n0 * frcp(d0); o.y = n1 * frcp(d1);
        upk2(nm3, n0, n1); upk2(dn3, d0, d1);
        o.z = n0 * frcp(d0); o.w = n1 * frcp(d1);
        ((float4*)out)[quad1] = o;
    }
}

// ---------------- launch ----------------
extern "C" void kernel_launch(void* const* d_in, const int* in_sizes, int n_in,
                              void* d_out, int out_size) {
    const float* x    = (const float*)d_in[0];
    const float* vals = (const float*)d_in[1];
    const float* pr   = (const float*)d_in[2];
    const float* pim  = (const float*)d_in[3];
    float* out = (float*)d_out;

    k_all<<<GRID, BLOCK>>>(x, vals, pr, pim, out);
}

// round 10
// speedup vs baseline: 1.1079x; 1.0495x over previous
#include <cuda_runtime.h>
#include <math.h>

#define NN       1024
#define NEVALC   131072
#define NPOLES   8
#define NGROUPS  256          // 4 nodes per group
#define GRID     128
#define BLOCK    512
#define LOGC     700.0f      // fixed log-shift (cancels in num/den); keeps expf in range

typedef unsigned long long ull;

// ---------------- compile-time Chebyshev nodes --------------------------------------
constexpr double CPI = 3.141592653589793238462643383279502884;
constexpr double ccos_t(double z) {            // |z| <= pi/4
    double t = 1.0, s = 1.0, z2 = z * z;
    for (int k = 1; k <= 12; k++) { t *= -z2 / ((2.0 * k - 1.0) * (2.0 * k)); s += t; }
    return s;
}
constexpr double csin_t(double z) {            // |z| <= pi/4
    double t = z, s = z, z2 = z * z;
    for (int k = 1; k <= 12; k++) { t *= -z2 / ((2.0 * k) * (2.0 * k + 1.0)); s += t; }
    return s;
}
constexpr double cospi_c(double x) {           // x in [0,1]
    double r = x; bool neg = false;
    if (r > 0.5) { r = 1.0 - r; neg = true; }
    double v = (r <= 0.25) ? ccos_t(CPI * r) : csin_t(CPI * (0.5 - r));
    return neg ? -v : v;
}
struct alignas(16) NodeTab { float v[NN]; };
constexpr NodeTab mk_nodes() {
    NodeTab n{};
    for (int i = 0; i < NN; i++) n.v[i] = (float)cospi_c((double)i / 1023.0);
    return n;
}
__device__ constexpr NodeTab c_nodes = mk_nodes();

// ---------------- scratch (no allocations allowed) ----------------
__device__ ulonglong2 g_coef[NGROUPS * 7];   // 14 packed-duplicated f32x2 coeffs per group
__device__ unsigned   g_bar;                  // monotonic grid-barrier ticket counter

// ---------------- packed f32x2 helpers (sm_103a) ----------------
__device__ __forceinline__ ull pk2(float lo, float hi) {
    ull r; asm("mov.b64 %0,{%1,%2};" : "=l"(r) : "f"(lo), "f"(hi)); return r;
}
__device__ __forceinline__ void upk2(ull v, float& lo, float& hi) {
    asm("mov.b64 {%0,%1},%2;" : "=f"(lo), "=f"(hi) : "l"(v));
}
__device__ __forceinline__ ull f2fma(ull a, ull b, ull c) {
    ull d; asm("fma.rn.f32x2 %0,%1,%2,%3;" : "=l"(d) : "l"(a), "l"(b), "l"(c)); return d;
}
__device__ __forceinline__ ull f2add(ull a, ull b) {
    ull d; asm("add.rn.f32x2 %0,%1,%2;" : "=l"(d) : "l"(a), "l"(b)); return d;
}
__device__ __forceinline__ ull f2mul(ull a, ull b) {
    ull d; asm("mul.rn.f32x2 %0,%1,%2;" : "=l"(d) : "l"(a), "l"(b)); return d;
}
__device__ __forceinline__ ull f2rcp(ull q) {
    ull r;
    asm("{.reg .f32 lo, hi;\n\t"
        "mov.b64 {lo, hi}, %1;\n\t"
        "rcp.approx.f32 lo, lo;\n\t"
        "rcp.approx.f32 hi, hi;\n\t"
        "mov.b64 %0, {lo, hi};}"
        : "=l"(r) : "l"(q));
    return r;
}
__device__ __forceinline__ float frcp(float a) {
    float r; asm("rcp.approx.f32 %0,%1;" : "=f"(r) : "f"(a)); return r;
}
__device__ __forceinline__ unsigned ldacq(unsigned* p) {
    unsigned v; asm volatile("ld.acquire.gpu.u32 %0,[%1];" : "=r"(v) : "l"(p)); return v;
}

// ---------------- fused kernel: prep + grid barrier + eval --------------------------
// grid 128 x block 512 -> 1 resident block per SM, so the software grid barrier
// cannot deadlock. Ticket counter is monotonic across graph replays.
__global__ __launch_bounds__(512) void k_all(const float* __restrict__ x,
                                             const float* __restrict__ vals,
                                             const float* __restrict__ pr,
                                             const float* __restrict__ pim,
                                             float* __restrict__ out) {
    __shared__ float snodes[NN];
    __shared__ float sw[8];
    __shared__ float spart[8];
    __shared__ ulonglong2 sc[NGROUPS * 7];     // 28 KB coeffs (later reused for reduction)

    int tid = threadIdx.x;
    int w   = tid >> 5;
    int ln  = tid & 31;

    // ---- node table from the compile-time constant ----
    ((float2*)snodes)[tid] = ((const float2*)c_nodes.v)[tid];
    __syncthreads();

    // ---- weights: 2 warps per node (block owns nodes 8b..8b+7) ----
    // f32 log-sum per reference; the max-normalization is a COMMON factor across
    // nodes and cancels in num/den -> fixed LOGC shift, no global reduction.
    {
        int j = blockIdx.x * 8 + (w & 7);
        int h = w >> 3;                        // which half of the i-range
        float nj = snodes[j];
        float s = 0.f;
        #pragma unroll 4
        for (int i = ln + 32 * h; i < NN; i += 64)
            if (i != j) s += logf(fabsf(nj - snodes[i]));
        #pragma unroll
        for (int off = 16; off; off >>= 1) s += __shfl_xor_sync(0xffffffffu, s, off);
        if (ln == 0 && h == 1) spart[w & 7] = s;
        __syncthreads();
        if (ln == 0 && h == 0) {
            s += spart[w];
            float ps = 0.f;
            #pragma unroll
            for (int p = 0; p < NPOLES; p++) {
                float dr = nj - pr[p];
                ps += logf(dr * dr + pim[p] * pim[p]);
            }
            float wv = expf(ps - s - LOGC);
            sw[w] = (j & 1) ? -wv : wv;        // sign = (-1)^j (nodes strictly descending)
        }
    }
    __syncthreads();

    // ---- group-rational coefficients (fp64, 4 lanes per group, 2 groups/block) ----
    //   Q(t)  = prod (t - d_i)                     (monic quartic)
    //   Pv(t) = sum v_i*w_i * prod_{j!=i}(t - d_j) (cubic)
    //   Pw(t) = sum     w_i * prod_{j!=i}(t - d_j) (cubic)
    if (tid < 8) {
        int g  = blockIdx.x * 2 + (tid >> 2);
        int i  = tid & 3;
        double n[4];
        #pragma unroll
        for (int k = 0; k < 4; k++) n[k] = (double)snodes[4 * g + k];
        float cf = (float)(0.25 * (n[0] + n[1] + n[2] + n[3]));
        double d[4];
        #pragma unroll
        for (int k = 0; k < 4; k++) d[k] = n[k] - (double)cf;
        double e1 = d[0] + d[1] + d[2] + d[3];
        double e2 = d[0]*d[1] + d[0]*d[2] + d[0]*d[3] + d[1]*d[2] + d[1]*d[3] + d[2]*d[3];
        double e3 = d[0]*d[1]*d[2] + d[0]*d[1]*d[3] + d[0]*d[2]*d[3] + d[1]*d[2]*d[3];
        double e4 = d[0]*d[1]*d[2]*d[3];
        double u  = (double)sw[(tid >> 2) * 4 + i];
        double uv = u * (double)vals[4 * g + i];
        double s1 = e1 - d[i];                 // elementary syms of the 3 other roots
        double s2 = e2 - d[i] * s1;
        double s3 = e3 - d[i] * s2;
        double red[8] = { uv, -uv * s1,  uv * s2, -uv * s3,
                          u,  -u  * s1,  u  * s2, -u  * s3 };
        #pragma unroll
        for (int k = 0; k < 8; k++) {
            red[k] += __shfl_down_sync(0xffu, red[k], 2, 4);
            red[k] += __shfl_down_sync(0xffu, red[k], 1, 4);
        }
        if (i == 0) {
            ull* cc = (ull*)g_coef + (size_t)g * 14;
            float f;
            f = -cf;              cc[0]  = pk2(f, f);
            f = (float)(-e1);     cc[1]  = pk2(f, f);   // q3
            f = (float)( e2);     cc[2]  = pk2(f, f);   // q2
            f = (float)(-e3);     cc[3]  = pk2(f, f);   // q1
            f = (float)( e4);     cc[4]  = pk2(f, f);   // q0
            f = (float)red[0];    cc[5]  = pk2(f, f);   // pv3
            f = (float)red[1];    cc[6]  = pk2(f, f);
            f = (float)red[2];    cc[7]  = pk2(f, f);
            f = (float)red[3];    cc[8]  = pk2(f, f);
            f = (float)red[4];    cc[9]  = pk2(f, f);   // pw3
            f = (float)red[5];    cc[10] = pk2(f, f);
            f = (float)red[6];    cc[11] = pk2(f, f);
            f = (float)red[7];    cc[12] = pk2(f, f);
            cc[13] = 0ull;
            __threadfence();                   // release own coeffs before barrier
        }
    }

    // ---- x loads (independent of coefficients; hide behind the barrier) ----
    int part  = tid >> 7;                      // group partition 0..3
    int lane  = tid & 127;                     // point-lane
    int quad0 = blockIdx.x * 256 + lane;       // coalesced float4 accesses
    int quad1 = quad0 + 128;
    float4 a = ((const float4*)x)[quad0];
    float4 b = ((const float4*)x)[quad1];
    ull xp0 = pk2(a.x, a.y), xp1 = pk2(a.z, a.w);
    ull xp2 = pk2(b.x, b.y), xp3 = pk2(b.z, b.w);

    // ---- grid barrier (monotonic tickets; 1 block/SM -> all resident) ----
    __syncthreads();
    if (tid == 0) {
        unsigned ticket = atomicAdd(&g_bar, 1u);
        unsigned target = (ticket / GRID + 1u) * GRID;
        while (ldacq(&g_bar) < target) { }
    }
    __syncthreads();

    // ---- load all 256 groups' coefficients into smem ----
    {
        const uint4* src = (const uint4*)g_coef;
        uint4* dst = (uint4*)sc;
        #pragma unroll
        for (int i = tid; i < NGROUPS * 7; i += BLOCK) dst[i] = src[i];
    }
    __syncthreads();

    // ---- eval: 8 pts/thread (4 packed pairs), split-4 over groups,
    //      RECIPROCAL MERGED across group pairs (i, i+32) within the partition:
    //      V_A/Q_A + V_B/Q_B = (V_A Q_B + V_B Q_A) / (Q_A Q_B)
    //      -> 1 packed rcp per 2 groups (halves MUFU, the measured bottleneck).
    //      Partner groups are 128 nodes apart, so Q_A*Q_B stays in normal f32
    //      range (min ~3e-27), and the rcp error cancels between num and den.
    ull nm0 = 0, dn0 = 0, nm1 = 0, dn1 = 0, nm2 = 0, dn2 = 0, nm3 = 0, dn3 = 0;
    const ulonglong2* cpA = sc + part * 64 * 7;
    const ulonglong2* cpB = cpA + 32 * 7;

    #pragma unroll 4
    for (int i = 0; i < 32; i++) {
        ulonglong2 a0 = cpA[0], a1 = cpA[1], a2 = cpA[2], a3 = cpA[3],
                   a4 = cpA[4], a5 = cpA[5], a6 = cpA[6];
        ulonglong2 b0 = cpB[0], b1 = cpB[1], b2 = cpB[2], b3 = cpB[3],
                   b4 = cpB[4], b5 = cpB[5], b6 = cpB[6];
        cpA += 7; cpB += 7;

        #define GRP2(XP, NM, DN)                                              \
        {                                                                     \
            ull tA = f2add(XP, a0.x);          /* t = x - c_A */              \
            ull tB = f2add(XP, b0.x);          /* t = x - c_B */              \
            ull qA = f2add(tA, a0.y);          /* monic quartic Horner A */   \
            qA = f2fma(qA, tA, a1.x);                                         \
            qA = f2fma(qA, tA, a1.y);                                         \
            qA = f2fma(qA, tA, a2.x);                                         \
            ull qB = f2add(tB, b0.y);          /* monic quartic Horner B */   \
            qB = f2fma(qB, tB, b1.x);                                         \
            qB = f2fma(qB, tB, b1.y);                                         \
            qB = f2fma(qB, tB, b2.x);                                         \
            ull vA = f2fma(a2.y, tA, a3.x);    /* cubic num A */              \
            vA = f2fma(vA, tA, a3.y);                                         \
            vA = f2fma(vA, tA, a4.x);                                         \
            ull vB = f2fma(b2.y, tB, b3.x);    /* cubic num B */              \
            vB = f2fma(vB, tB, b3.y);                                         \
            vB = f2fma(vB, tB, b4.x);                                         \
            ull wA = f2fma(a4.y, tA, a5.x);    /* cubic den A */              \
            wA = f2fma(wA, tA, a5.y);                                         \
            wA = f2fma(wA, tA, a6.x);                                         \
            ull wB = f2fma(b4.y, tB, b5.x);    /* cubic den B */              \
            wB = f2fma(wB, tB, b5.y);                                         \
            wB = f2fma(wB, tB, b6.x);                                         \
            ull qq = f2mul(qA, qB);                                           \
            ull r  = f2rcp(qq);                /* 1 packed rcp / 2 groups */  \
            ull vc = f2mul(vA, qB);                                           \
            vc = f2fma(vB, qA, vc);                                           \
            ull wc = f2mul(wA, qB);                                           \
            wc = f2fma(wB, qA, wc);                                           \
            NM = f2fma(vc, r, NM);                                            \
            DN = f2fma(wc, r, DN);                                            \
        }
        GRP2(xp0, nm0, dn0)
        GRP2(xp1, nm1, dn1)
        GRP2(xp2, nm2, dn2)
        GRP2(xp3, nm3, dn3)
        #undef GRP2
    }

    // ---- cross-partition reduction (reuse sc) + divide + store ----
    __syncthreads();
    ull (*sred)[128][8] = (ull(*)[128][8])sc;   // 3 x 128 x 8 x 8B = 24 KB <= 28 KB
    if (part) {
        ull* dst = sred[part - 1][lane];
        dst[0] = nm0; dst[1] = dn0; dst[2] = nm1; dst[3] = dn1;
        dst[4] = nm2; dst[5] = dn2; dst[6] = nm3; dst[7] = dn3;
    }
    __syncthreads();
    if (part == 0) {
        #pragma unroll
        for (int p = 0; p < 3; p++) {
            const ull* s = sred[p][lane];
            nm0 = f2add(nm0, s[0]); dn0 = f2add(dn0, s[1]);
            nm1 = f2add(nm1, s[2]); dn1 = f2add(dn1, s[3]);
            nm2 = f2add(nm2, s[4]); dn2 = f2add(dn2, s[5]);
            nm3 = f2add(nm3, s[6]); dn3 = f2add(dn3, s[7]);
        }
        float n0, n1, d0, d1;
        float4 o;
        upk2(nm0, n0, n1); upk2(dn0, d0, d1);
        o.x = n0 * frcp(d0); o.y = n1 * frcp(d1);
        upk2(nm1, n0, n1); upk2(dn1, d0, d1);
        o.z = n0 * frcp(d0); o.w = n1 * frcp(d1);
        ((float4*)out)[quad0] = o;
        upk2(nm2, n0, n1); upk2(dn2, d0, d1);
        o.x = n0 * frcp(d0); o.y = n1 * frcp(d1);
        upk2(nm3, n0, n1); upk2(dn3, d0, d1);
        o.z = n0 * frcp(d0); o.w = n1 * frcp(d1);
        ((float4*)out)[quad1] = o;
    }
}

// ---------------- launch ----------------
extern "C" void kernel_launch(void* const* d_in, const int* in_sizes, int n_in,
                              void* d_out, int out_size) {
    const float* x    = (const float*)d_in[0];
    const float* vals = (const float*)d_in[1];
    const float* pr   = (const float*)d_in[2];
    const float* pim  = (const float*)d_in[3];
    float* out = (float*)d_out;

    k_all<<<GRID, BLOCK>>>(x, vals, pr, pim, out);
}